// round 2
// baseline (speedup 1.0000x reference)
#include <cuda_runtime.h>
#include <math.h>
#include <stdint.h>

#define BB 2
#define TT 2048
#define DD 1024
#define HH 16
#define HD 64
#define MROWS (BB*TT)   // 4096

// Scratch buffers (allocation-free rule: __device__ globals)
__device__ float g_q[MROWS*DD];
__device__ float g_k[MROWS*DD];
__device__ float g_v[MROWS*DD];
__device__ float g_att[MROWS*DD];

// ---------------------------------------------------------------------------
// 3xTF32 tensor-core GEMM: C[M,N] = A[M,K] @ W[K,N] + bias[N]  (fp32 in/out)
// Tile 128x128, BK=16, 256 threads (8 warps, 2x4), warp tile 64x32,
// mma.sync.m16n8k8.tf32 with hi/lo error compensation (fp32-grade accuracy).
// ---------------------------------------------------------------------------
#define LKK 16
#define SAP 136   // smem row stride: (k*136+m)%32 == (k*8+m)%32 -> conflict-free frags

__device__ __forceinline__ uint32_t f2tf32(float x) {
    uint32_t r;
    asm("cvt.rna.tf32.f32 %0, %1;" : "=r"(r) : "f"(x));
    return r;
}

#define MMA_TF32(c, a, b) \
  asm volatile("mma.sync.aligned.m16n8k8.row.col.f32.tf32.tf32.f32 " \
    "{%0,%1,%2,%3}, {%4,%5,%6,%7}, {%8,%9}, {%0,%1,%2,%3};" \
    : "+f"((c)[0]), "+f"((c)[1]), "+f"((c)[2]), "+f"((c)[3]) \
    : "r"((a)[0]), "r"((a)[1]), "r"((a)[2]), "r"((a)[3]), \
      "r"((b)[0]), "r"((b)[1]))

__global__ __launch_bounds__(256, 1) void gemm_tf32_kernel(
    const float* __restrict__ A, const float* __restrict__ W,
    const float* __restrict__ bias, float* __restrict__ C,
    int M, int N, int K)
{
    __shared__ float Ah[LKK*SAP], Al[LKK*SAP];
    __shared__ float Bh[LKK*SAP], Bl[LKK*SAP];

    const int tid  = threadIdx.x;
    const int lane = tid & 31;
    const int wid  = tid >> 5;
    const int wm   = wid >> 2;        // 0..1
    const int wn   = wid & 3;         // 0..3
    const int lr   = lane >> 2;       // 0..7
    const int lc   = lane & 3;        // 0..3
    const int m0   = blockIdx.y * 128;
    const int n0   = blockIdx.x * 128;

    // loader indices
    const int arow = tid >> 2;          // 0..63
    const int acol = (tid & 3) << 2;    // 0,4,8,12
    const int brow = tid >> 4;          // 0..15
    const int bcol = (tid & 15) << 2;   // 0..60

    float c[4][4][4];
    #pragma unroll
    for (int mt = 0; mt < 4; mt++)
        #pragma unroll
        for (int nt = 0; nt < 4; nt++)
            #pragma unroll
            for (int i = 0; i < 4; i++) c[mt][nt][i] = 0.f;

    const float* Ap0 = A + (size_t)(m0 + arow) * K + acol;
    const float* Ap1 = A + (size_t)(m0 + arow + 64) * K + acol;
    const float* Bp  = W + (size_t)brow * N + n0 + bcol;

    float4 a0v = *(const float4*)Ap0;
    float4 a1v = *(const float4*)Ap1;
    float4 b0v = *(const float4*)Bp;
    float4 b1v = *(const float4*)(Bp + 64);

    for (int kt = 0; kt < K; kt += LKK) {
        // ---- store staged tile to smem with hi/lo TF32 split ----
        #pragma unroll
        for (int i = 0; i < 4; i++) {
            float x0 = (&a0v.x)[i];
            float h0 = __uint_as_float(f2tf32(x0));
            Ah[(acol + i) * SAP + arow] = h0;
            Al[(acol + i) * SAP + arow] = __uint_as_float(f2tf32(x0 - h0));
            float x1 = (&a1v.x)[i];
            float h1 = __uint_as_float(f2tf32(x1));
            Ah[(acol + i) * SAP + arow + 64] = h1;
            Al[(acol + i) * SAP + arow + 64] = __uint_as_float(f2tf32(x1 - h1));
            float y0 = (&b0v.x)[i];
            float g0 = __uint_as_float(f2tf32(y0));
            Bh[brow * SAP + bcol + i] = g0;
            Bl[brow * SAP + bcol + i] = __uint_as_float(f2tf32(y0 - g0));
            float y1 = (&b1v.x)[i];
            float g1 = __uint_as_float(f2tf32(y1));
            Bh[brow * SAP + bcol + 64 + i] = g1;
            Bl[brow * SAP + bcol + 64 + i] = __uint_as_float(f2tf32(y1 - g1));
        }
        __syncthreads();

        // ---- prefetch next tile while computing ----
        if (kt + LKK < K) {
            a0v = *(const float4*)(Ap0 + kt + LKK);
            a1v = *(const float4*)(Ap1 + kt + LKK);
            b0v = *(const float4*)(Bp + (size_t)(kt + LKK) * N);
            b1v = *(const float4*)(Bp + (size_t)(kt + LKK) * N + 64);
        }

        // ---- compute: two k-substeps of 8 ----
        #pragma unroll
        for (int ks = 0; ks < LKK; ks += 8) {
            uint32_t ah[4][4], al_[4][4], bh[4][2], bl_[4][2];
            const int k0i = (ks + lc) * SAP;
            const int k1i = (ks + lc + 4) * SAP;
            #pragma unroll
            for (int mt = 0; mt < 4; mt++) {
                const int m = wm * 64 + mt * 16 + lr;
                ah[mt][0]  = __float_as_uint(Ah[k0i + m]);
                ah[mt][1]  = __float_as_uint(Ah[k0i + m + 8]);
                ah[mt][2]  = __float_as_uint(Ah[k1i + m]);
                ah[mt][3]  = __float_as_uint(Ah[k1i + m + 8]);
                al_[mt][0] = __float_as_uint(Al[k0i + m]);
                al_[mt][1] = __float_as_uint(Al[k0i + m + 8]);
                al_[mt][2] = __float_as_uint(Al[k1i + m]);
                al_[mt][3] = __float_as_uint(Al[k1i + m + 8]);
            }
            #pragma unroll
            for (int nt = 0; nt < 4; nt++) {
                const int n = wn * 32 + nt * 8 + lr;
                bh[nt][0]  = __float_as_uint(Bh[k0i + n]);
                bh[nt][1]  = __float_as_uint(Bh[k1i + n]);
                bl_[nt][0] = __float_as_uint(Bl[k0i + n]);
                bl_[nt][1] = __float_as_uint(Bl[k1i + n]);
            }
            #pragma unroll
            for (int mt = 0; mt < 4; mt++)
                #pragma unroll
                for (int nt = 0; nt < 4; nt++) {
                    MMA_TF32(c[mt][nt], ah[mt], bh[nt]);
                    MMA_TF32(c[mt][nt], ah[mt], bl_[nt]);
                    MMA_TF32(c[mt][nt], al_[mt], bh[nt]);
                }
        }
        __syncthreads();
    }

    // ---- epilogue: bias + store ----
    #pragma unroll
    for (int mt = 0; mt < 4; mt++) {
        const int row = m0 + wm * 64 + mt * 16 + lr;
        #pragma unroll
        for (int nt = 0; nt < 4; nt++) {
            const int col = n0 + wn * 32 + nt * 8 + 2 * lc;
            float2 r0, r1;
            r0.x = c[mt][nt][0] + bias[col];
            r0.y = c[mt][nt][1] + bias[col + 1];
            r1.x = c[mt][nt][2] + bias[col];
            r1.y = c[mt][nt][3] + bias[col + 1];
            *(float2*)(C + (size_t)row * N + col)       = r0;
            *(float2*)(C + (size_t)(row + 8) * N + col) = r1;
        }
    }
}

// ---------------------------------------------------------------------------
// Flash-style causal attention v2 (fp32, hd=64).
// 256 threads / 128 query rows: lane pairs split HD (32 dims each),
// partial QK dot combined via shfl_xor(1). 16 warps/SM (2 blocks).
// ---------------------------------------------------------------------------
#define AM 128
#define AN 64
#define ATTN_SMEM ((2*AN*HD + AM*(AN+1)) * 4)  // 66048 bytes

__global__ __launch_bounds__(256, 2) void attn_kernel(
    const float* __restrict__ Q, const float* __restrict__ Kg,
    const float* __restrict__ Vg, float* __restrict__ O)
{
    extern __shared__ float sm[];
    float* Ks = sm;                 // [AN][HD]
    float* Vs = sm + AN * HD;       // [AN][HD]
    float* Ss = sm + 2 * AN * HD;   // [AM][AN+1]

    const int tid  = threadIdx.x;
    const int qr   = tid >> 1;        // 0..127
    const int half = tid & 1;
    const int db   = half * 32;       // this thread's HD half
    // reverse tile order: heavy causal tiles first (load balance)
    const int qtile = (gridDim.x - 1) - blockIdx.x;
    const int q0   = qtile * AM;
    const int b    = blockIdx.y >> 4;
    const int h    = blockIdx.y & 15;
    const int q_idx = q0 + qr;

    // this thread's half of the query row
    const float* qp = Q + ((size_t)(b * TT + q_idx)) * DD + h * HD + db;
    float q[32];
    #pragma unroll
    for (int d = 0; d < 32; d += 4) {
        float4 t4 = *(const float4*)(qp + d);
        q[d] = t4.x; q[d+1] = t4.y; q[d+2] = t4.z; q[d+3] = t4.w;
    }

    float o[32];
    #pragma unroll
    for (int d = 0; d < 32; d++) o[d] = 0.f;
    float mval = -1e30f, l = 0.f;

    float* srow = Ss + qr * (AN + 1);
    const int nt = q0 / AN + 2;   // causal: tiles needed

    for (int kt = 0; kt < nt; kt++) {
        __syncthreads();   // protect previous tile reads
        const int sbase = kt * AN;
        const float* kg = Kg + ((size_t)(b * TT + sbase)) * DD + h * HD;
        const float* vg = Vg + ((size_t)(b * TT + sbase)) * DD + h * HD;

        // cooperative K/V tile load (1024 float4 each, 256 threads)
        for (int i = tid; i < AN * HD / 4; i += 256) {
            const int r = i >> 4;
            const int c = (i & 15) << 2;
            *(float4*)(Ks + r * HD + c) = *(const float4*)(kg + (size_t)r * DD + c);
            *(float4*)(Vs + r * HD + c) = *(const float4*)(vg + (size_t)r * DD + c);
        }
        __syncthreads();

        // scores: partial dot over this half, combine with lane pair
        float tmax = -1e30f;
        for (int j = 0; j < AN; j++) {
            const float* kr = Ks + j * HD + db;
            float s = 0.f;
            #pragma unroll
            for (int d = 0; d < 32; d += 4) {
                float4 k4 = *(const float4*)(kr + d);
                s += q[d]   * k4.x;
                s += q[d+1] * k4.y;
                s += q[d+2] * k4.z;
                s += q[d+3] * k4.w;
            }
            s += __shfl_xor_sync(0xffffffffu, s, 1);
            s *= 0.125f;                        // hd^-0.5
            if (sbase + j > q_idx) s = -1e30f;  // causal mask
            srow[j] = s;                        // both lanes write same value
            tmax = fmaxf(tmax, s);
        }

        // online softmax rescale
        const float mnew  = fmaxf(mval, tmax);
        const float alpha = __expf(mval - mnew);
        l *= alpha;
        #pragma unroll
        for (int d = 0; d < 32; d++) o[d] *= alpha;

        for (int j = 0; j < AN; j++) {
            const float p = __expf(srow[j] - mnew);
            l += p;
            const float* vr = Vs + j * HD + db;
            #pragma unroll
            for (int d = 0; d < 32; d += 4) {
                float4 v4 = *(const float4*)(vr + d);
                o[d]   += p * v4.x;
                o[d+1] += p * v4.y;
                o[d+2] += p * v4.z;
                o[d+3] += p * v4.w;
            }
        }
        mval = mnew;
    }

    const float inv = 1.f / l;
    float* op = O + ((size_t)(b * TT + q_idx)) * DD + h * HD + db;
    #pragma unroll
    for (int d = 0; d < 32; d += 4) {
        float4 r4 = make_float4(o[d] * inv, o[d+1] * inv, o[d+2] * inv, o[d+3] * inv);
        *(float4*)(op + d) = r4;
    }
}

// ---------------------------------------------------------------------------
extern "C" void kernel_launch(void* const* d_in, const int* in_sizes, int n_in,
                              void* d_out, int out_size)
{
    (void)in_sizes; (void)n_in; (void)out_size;
    const float* x  = (const float*)d_in[0];
    // d_in[1] = mask (pure causal, applied analytically in-kernel)
    const float* Wq = (const float*)d_in[2];
    const float* bq = (const float*)d_in[3];
    const float* Wk = (const float*)d_in[4];
    const float* bk = (const float*)d_in[5];
    const float* Wv = (const float*)d_in[6];
    const float* bv = (const float*)d_in[7];
    const float* Wo = (const float*)d_in[8];
    const float* bo = (const float*)d_in[9];
    float* out = (float*)d_out;

    float *q, *k, *v, *att;
    cudaGetSymbolAddress((void**)&q,   g_q);
    cudaGetSymbolAddress((void**)&k,   g_k);
    cudaGetSymbolAddress((void**)&v,   g_v);
    cudaGetSymbolAddress((void**)&att, g_att);

    cudaFuncSetAttribute(attn_kernel,
                         cudaFuncAttributeMaxDynamicSharedMemorySize, ATTN_SMEM);

    dim3 gg(DD / 128, MROWS / 128);   // (8, 32)
    gemm_tf32_kernel<<<gg, 256>>>(x, Wq, bq, q, MROWS, DD, DD);
    gemm_tf32_kernel<<<gg, 256>>>(x, Wk, bk, k, MROWS, DD, DD);
    gemm_tf32_kernel<<<gg, 256>>>(x, Wv, bv, v, MROWS, DD, DD);

    attn_kernel<<<dim3(TT / AM, BB * HH), 256, ATTN_SMEM>>>(q, k, v, att);

    gemm_tf32_kernel<<<gg, 256>>>(att, Wo, bo, out, MROWS, DD, DD);
}

// round 4
// speedup vs baseline: 1.6778x; 1.6778x over previous
#include <cuda_runtime.h>
#include <cuda_bf16.h>
#include <math.h>
#include <stdint.h>

#define BB 2
#define TT 2048
#define DD 1024
#define HH 16
#define HD 64
#define MROWS (BB*TT)   // 4096

// ---------------------------------------------------------------------------
// Scratch (__device__ globals per allocation-free rule)
// ---------------------------------------------------------------------------
__device__ float g_q[MROWS*DD];
__device__ float g_k[MROWS*DD];
__device__ float g_v[MROWS*DD];
__device__ float g_att[MROWS*DD];

__device__ __nv_bfloat16 g_x0[MROWS*DD], g_x1[MROWS*DD];   // x split hi/lo
__device__ __nv_bfloat16 g_a0[MROWS*DD], g_a1[MROWS*DD];   // att split hi/lo
// transposed+split weights: [N=1024 rows, K=1024] bf16
__device__ __nv_bfloat16 g_wq0[DD*DD], g_wq1[DD*DD];
__device__ __nv_bfloat16 g_wk0[DD*DD], g_wk1[DD*DD];
__device__ __nv_bfloat16 g_wv0[DD*DD], g_wv1[DD*DD];
__device__ __nv_bfloat16 g_wo0[DD*DD], g_wo1[DD*DD];

// ---------------------------------------------------------------------------
// PTX helpers (baseline sm_103 ISA only: cp.async / ldmatrix / mma.sync)
// ---------------------------------------------------------------------------
__device__ __forceinline__ uint32_t smem_u32(const void* p) {
    uint32_t a;
    asm("{ .reg .u64 t; cvta.to.shared.u64 t, %1; cvt.u32.u64 %0, t; }"
        : "=r"(a) : "l"(p));
    return a;
}

#define CP16(dst, src) \
    asm volatile("cp.async.cg.shared.global [%0], [%1], 16;" \
        :: "r"(dst), "l"(src) : "memory")
#define CP_COMMIT() asm volatile("cp.async.commit_group;" ::: "memory")
#define CP_WAIT1()  asm volatile("cp.async.wait_group 1;" ::: "memory")
#define CP_WAIT0()  asm volatile("cp.async.wait_group 0;" ::: "memory")

#define LDSM_X4(r, a) \
    asm volatile("ldmatrix.sync.aligned.m8n8.x4.shared.b16 {%0,%1,%2,%3}, [%4];" \
        : "=r"((r)[0]), "=r"((r)[1]), "=r"((r)[2]), "=r"((r)[3]) : "r"(a))
#define LDSM_X2(r, a) \
    asm volatile("ldmatrix.sync.aligned.m8n8.x2.shared.b16 {%0,%1}, [%2];" \
        : "=r"((r)[0]), "=r"((r)[1]) : "r"(a))

#define MMA_BF16(c, a, b) \
    asm volatile("mma.sync.aligned.m16n8k16.row.col.f32.bf16.bf16.f32 " \
        "{%0,%1,%2,%3}, {%4,%5,%6,%7}, {%8,%9}, {%0,%1,%2,%3};" \
        : "+f"((c)[0]), "+f"((c)[1]), "+f"((c)[2]), "+f"((c)[3]) \
        : "r"((a)[0]), "r"((a)[1]), "r"((a)[2]), "r"((a)[3]), \
          "r"((b)[0]), "r"((b)[1]))

// ---------------------------------------------------------------------------
// Prep kernels
// ---------------------------------------------------------------------------
__global__ void fsplit_kernel(const float* __restrict__ X,
                              __nv_bfloat16* __restrict__ H,
                              __nv_bfloat16* __restrict__ L)
{
    const int i = (blockIdx.x * blockDim.x + threadIdx.x) * 4;
    float4 xv = *(const float4*)(X + i);
    __nv_bfloat16 h[4], l[4];
    #pragma unroll
    for (int j = 0; j < 4; j++) {
        float x = (&xv.x)[j];
        h[j] = __float2bfloat16(x);
        l[j] = __float2bfloat16(x - __bfloat162float(h[j]));
    }
    *(__nv_bfloat162*)(H + i)     = __nv_bfloat162(h[0], h[1]);
    *(__nv_bfloat162*)(H + i + 2) = __nv_bfloat162(h[2], h[3]);
    *(__nv_bfloat162*)(L + i)     = __nv_bfloat162(l[0], l[1]);
    *(__nv_bfloat162*)(L + i + 2) = __nv_bfloat162(l[2], l[3]);
}

// W[K,N] fp32 -> Wt[N,K] bf16 hi/lo
__global__ void tsplit_kernel(const float* __restrict__ W,
                              __nv_bfloat16* __restrict__ Th,
                              __nv_bfloat16* __restrict__ Tl)
{
    __shared__ float t[32][33];
    const int n0 = blockIdx.x * 32, k0 = blockIdx.y * 32;
    const int tx = threadIdx.x, ty = threadIdx.y;   // 32 x 8
    #pragma unroll
    for (int i = 0; i < 32; i += 8)
        t[ty + i][tx] = W[(size_t)(k0 + ty + i) * DD + n0 + tx];
    __syncthreads();
    #pragma unroll
    for (int i = 0; i < 32; i += 8) {
        float x = t[tx][ty + i];                  // W[k0+tx][n0+ty+i]
        __nv_bfloat16 h = __float2bfloat16(x);
        const size_t o = (size_t)(n0 + ty + i) * DD + k0 + tx;
        Th[o] = h;
        Tl[o] = __float2bfloat16(x - __bfloat162float(h));
    }
}

// ---------------------------------------------------------------------------
// bf16 HMMA GEMM with 3-term split:
//   C[M,N] = (A0+A1)[M,K] @ (B0+B1)[N,K]^T + bias   (fp32 out)
// 128x128 tile/CTA, BK=32, cp.async double buffer, ldmatrix fragments,
// mma.sync.m16n8k16. 256 threads = 8 warps (2x4), warp tile 64x32.
// ---------------------------------------------------------------------------
#define GM 128
#define GN 128
#define GBK 32
#define NKT (DD / GBK)      // 32
#define SSTRB 80            // smem row stride in BYTES (32 bf16 = 64B + 16B pad)
#define OMAT (128 * SSTRB)  // 10240 B per matrix tile
#define OA0 0
#define OA1 (OMAT)
#define OB0 (2*OMAT)
#define OB1 (3*OMAT)
#define STAGE (4*OMAT)      // 40960 B
#define GEMM_SMEM (2*STAGE) // 81920 B

__global__ __launch_bounds__(256, 1) void gemm_bf16_kernel(
    const __nv_bfloat16* __restrict__ A0, const __nv_bfloat16* __restrict__ A1,
    const __nv_bfloat16* __restrict__ B0, const __nv_bfloat16* __restrict__ B1,
    const float* __restrict__ bias, float* __restrict__ C)
{
    extern __shared__ char smem[];
    const uint32_t sb = smem_u32(smem);
    const int tid  = threadIdx.x;
    const int wid  = tid >> 5;
    const int lane = tid & 31;
    const int wm   = wid >> 2;       // 0..1
    const int wn   = wid & 3;        // 0..3
    const int lr   = lane >> 2;      // 0..7
    const int lc   = lane & 3;       // 0..3
    const int m0 = blockIdx.y * GM;
    const int n0 = blockIdx.x * GN;

    // ---- loader mapping: thread loads 32B of one row per matrix ----
    const int lrow = tid >> 1;              // 0..127
    const int lcb  = (tid & 1) * 32;        // byte col offset: 0 or 32
    const uint32_t dstoff = lrow * SSTRB + lcb;
    const __nv_bfloat16* gA0 = A0 + (size_t)(m0 + lrow) * DD + lcb / 2;
    const __nv_bfloat16* gA1 = A1 + (size_t)(m0 + lrow) * DD + lcb / 2;
    const __nv_bfloat16* gB0 = B0 + (size_t)(n0 + lrow) * DD + lcb / 2;
    const __nv_bfloat16* gB1 = B1 + (size_t)(n0 + lrow) * DD + lcb / 2;

    // ---- fragment smem addresses (ldmatrix) ----
    // A: row = wm*64 + mt*16 + lane%16 ; 16B half select = lane/16 ; +ks*32B
    const uint32_t a_base = sb + (uint32_t)(wm * 64 + (lane & 15)) * SSTRB
                          + (uint32_t)(lane >> 4) * 16;
    // B: row = wn*32 + nt*8 + lane%8 ; 16B half = (lane>>3)&1 ; +ks*32B
    const uint32_t b_base = sb + OB0 + (uint32_t)(wn * 32 + (lane & 7)) * SSTRB
                          + (uint32_t)((lane >> 3) & 1) * 16;

    float c[4][4][4];
    #pragma unroll
    for (int mt = 0; mt < 4; mt++)
        #pragma unroll
        for (int nt = 0; nt < 4; nt++)
            #pragma unroll
            for (int i = 0; i < 4; i++) c[mt][nt][i] = 0.f;

    // ---- prologue: stage 0 ----
    {
        const uint32_t s = sb + dstoff;
        CP16(s + OA0,      gA0);      CP16(s + OA0 + 16, gA0 + 8);
        CP16(s + OA1,      gA1);      CP16(s + OA1 + 16, gA1 + 8);
        CP16(s + OB0,      gB0);      CP16(s + OB0 + 16, gB0 + 8);
        CP16(s + OB1,      gB1);      CP16(s + OB1 + 16, gB1 + 8);
        CP_COMMIT();
    }

    for (int kt = 0; kt < NKT; kt++) {
        // prefetch next stage
        if (kt + 1 < NKT) {
            const uint32_t s = sb + ((kt + 1) & 1) * STAGE + dstoff;
            const int ko = (kt + 1) * GBK;
            CP16(s + OA0,      gA0 + ko);  CP16(s + OA0 + 16, gA0 + ko + 8);
            CP16(s + OA1,      gA1 + ko);  CP16(s + OA1 + 16, gA1 + ko + 8);
            CP16(s + OB0,      gB0 + ko);  CP16(s + OB0 + 16, gB0 + ko + 8);
            CP16(s + OB1,      gB1 + ko);  CP16(s + OB1 + 16, gB1 + ko + 8);
            CP_COMMIT();
            CP_WAIT1();
        } else {
            CP_WAIT0();
        }
        __syncthreads();

        const uint32_t st = ((uint32_t)(kt & 1)) * STAGE;
        #pragma unroll
        for (int ks = 0; ks < 2; ks++) {
            const uint32_t ksb = st + ks * 32;
            uint32_t ah[4][4], al[4][4], bh[4][2], bl[4][2];
            #pragma unroll
            for (int mt = 0; mt < 4; mt++) {
                const uint32_t aa = a_base + ksb + (uint32_t)(mt * 16) * SSTRB;
                LDSM_X4(ah[mt], aa + OA0);
                LDSM_X4(al[mt], aa + OA1);
            }
            #pragma unroll
            for (int nt = 0; nt < 4; nt++) {
                const uint32_t ba = b_base + ksb + (uint32_t)(nt * 8) * SSTRB;
                LDSM_X2(bh[nt], ba);              // b_base already includes OB0
                LDSM_X2(bl[nt], ba + OMAT);       // OB1 = OB0 + OMAT
            }
            #pragma unroll
            for (int mt = 0; mt < 4; mt++)
                #pragma unroll
                for (int nt = 0; nt < 4; nt++) {
                    MMA_BF16(c[mt][nt], ah[mt], bh[nt]);
                    MMA_BF16(c[mt][nt], ah[mt], bl[nt]);
                    MMA_BF16(c[mt][nt], al[mt], bh[nt]);
                }
        }
        __syncthreads();
    }

    // ---- epilogue: bias + fp32 store ----
    #pragma unroll
    for (int mt = 0; mt < 4; mt++) {
        const int row = m0 + wm * 64 + mt * 16 + lr;
        #pragma unroll
        for (int nt = 0; nt < 4; nt++) {
            const int col = n0 + wn * 32 + nt * 8 + 2 * lc;
            float2 r0, r1;
            r0.x = c[mt][nt][0] + bias[col];
            r0.y = c[mt][nt][1] + bias[col + 1];
            r1.x = c[mt][nt][2] + bias[col];
            r1.y = c[mt][nt][3] + bias[col + 1];
            *(float2*)(C + (size_t)row * DD + col)       = r0;
            *(float2*)(C + (size_t)(row + 8) * DD + col) = r1;
        }
    }
}

// ---------------------------------------------------------------------------
// Flash-style causal attention (round-1 base + ILP fixes in dot/PV loops)
// ---------------------------------------------------------------------------
#define AM 128
#define AN 64
#define ATTN_SMEM ((2*AN*HD + AM*(AN+1)) * 4)  // 66048 bytes

__global__ __launch_bounds__(128, 2) void attn_kernel(
    const float* __restrict__ Q, const float* __restrict__ Kg,
    const float* __restrict__ Vg, float* __restrict__ O)
{
    extern __shared__ float sm[];
    float* Ks = sm;                 // [AN][HD]
    float* Vs = sm + AN * HD;       // [AN][HD]
    float* Ss = sm + 2 * AN * HD;   // [AM][AN+1]

    const int tid = threadIdx.x;
    const int q0  = blockIdx.x * AM;
    const int b   = blockIdx.y >> 4;
    const int h   = blockIdx.y & 15;
    const int q_idx = q0 + tid;

    const float* qp = Q + ((size_t)(b * TT + q_idx)) * DD + h * HD;
    float q[HD];
    #pragma unroll
    for (int d = 0; d < HD; d += 4) {
        float4 t4 = *(const float4*)(qp + d);
        q[d] = t4.x; q[d+1] = t4.y; q[d+2] = t4.z; q[d+3] = t4.w;
    }

    float o[HD];
    #pragma unroll
    for (int d = 0; d < HD; d++) o[d] = 0.f;
    float mval = -1e30f, l = 0.f;

    float* srow = Ss + tid * (AN + 1);
    const int nt = q0 / AN + 2;

    for (int kt = 0; kt < nt; kt++) {
        __syncthreads();
        const int sbase = kt * AN;
        const float* kg = Kg + ((size_t)(b * TT + sbase)) * DD + h * HD;
        const float* vg = Vg + ((size_t)(b * TT + sbase)) * DD + h * HD;

        for (int i = tid; i < AN * HD / 4; i += AM) {
            const int r = i >> 4;
            const int c = (i & 15) << 2;
            *(float4*)(Ks + r * HD + c) = *(const float4*)(kg + (size_t)r * DD + c);
            *(float4*)(Vs + r * HD + c) = *(const float4*)(vg + (size_t)r * DD + c);
        }
        __syncthreads();

        // scores: 4 independent accumulator chains per j, j unrolled 2x
        float tmax = -1e30f;
        #pragma unroll 2
        for (int j = 0; j < AN; j++) {
            const float* kr = Ks + j * HD;
            float s0 = 0.f, s1 = 0.f, s2 = 0.f, s3 = 0.f;
            #pragma unroll
            for (int d = 0; d < HD; d += 16) {
                float4 k0 = *(const float4*)(kr + d);
                float4 k1 = *(const float4*)(kr + d + 4);
                float4 k2 = *(const float4*)(kr + d + 8);
                float4 k3 = *(const float4*)(kr + d + 12);
                s0 += q[d]    * k0.x; s0 += q[d+1]  * k0.y;
                s0 += q[d+2]  * k0.z; s0 += q[d+3]  * k0.w;
                s1 += q[d+4]  * k1.x; s1 += q[d+5]  * k1.y;
                s1 += q[d+6]  * k1.z; s1 += q[d+7]  * k1.w;
                s2 += q[d+8]  * k2.x; s2 += q[d+9]  * k2.y;
                s2 += q[d+10] * k2.z; s2 += q[d+11] * k2.w;
                s3 += q[d+12] * k3.x; s3 += q[d+13] * k3.y;
                s3 += q[d+14] * k3.z; s3 += q[d+15] * k3.w;
            }
            float s = ((s0 + s1) + (s2 + s3)) * 0.125f;
            if (sbase + j > q_idx) s = -1e30f;
            srow[j] = s;
            tmax = fmaxf(tmax, s);
        }

        const float mnew  = fmaxf(mval, tmax);
        const float alpha = __expf(mval - mnew);
        l *= alpha;
        #pragma unroll
        for (int d = 0; d < HD; d++) o[d] *= alpha;

        #pragma unroll 2
        for (int j = 0; j < AN; j++) {
            const float p = __expf(srow[j] - mnew);
            l += p;
            const float* vr = Vs + j * HD;
            #pragma unroll
            for (int d = 0; d < HD; d += 4) {
                float4 v4 = *(const float4*)(vr + d);
                o[d]   += p * v4.x;
                o[d+1] += p * v4.y;
                o[d+2] += p * v4.z;
                o[d+3] += p * v4.w;
            }
        }
        mval = mnew;
    }

    const float inv = 1.f / l;
    float* op = O + ((size_t)(b * TT + q_idx)) * DD + h * HD;
    #pragma unroll
    for (int d = 0; d < HD; d += 4) {
        float4 r4 = make_float4(o[d] * inv, o[d+1] * inv, o[d+2] * inv, o[d+3] * inv);
        *(float4*)(op + d) = r4;
    }
}

// ---------------------------------------------------------------------------
extern "C" void kernel_launch(void* const* d_in, const int* in_sizes, int n_in,
                              void* d_out, int out_size)
{
    (void)in_sizes; (void)n_in; (void)out_size;
    const float* x  = (const float*)d_in[0];
    const float* Wq = (const float*)d_in[2];
    const float* bq = (const float*)d_in[3];
    const float* Wk = (const float*)d_in[4];
    const float* bk = (const float*)d_in[5];
    const float* Wv = (const float*)d_in[6];
    const float* bv = (const float*)d_in[7];
    const float* Wo = (const float*)d_in[8];
    const float* bo = (const float*)d_in[9];
    float* out = (float*)d_out;

    float *q, *k, *v, *att;
    cudaGetSymbolAddress((void**)&q,   g_q);
    cudaGetSymbolAddress((void**)&k,   g_k);
    cudaGetSymbolAddress((void**)&v,   g_v);
    cudaGetSymbolAddress((void**)&att, g_att);
    __nv_bfloat16 *x0, *x1, *a0, *a1;
    cudaGetSymbolAddress((void**)&x0, g_x0);
    cudaGetSymbolAddress((void**)&x1, g_x1);
    cudaGetSymbolAddress((void**)&a0, g_a0);
    cudaGetSymbolAddress((void**)&a1, g_a1);
    __nv_bfloat16 *wq0, *wq1, *wk0, *wk1, *wv0, *wv1, *wo0, *wo1;
    cudaGetSymbolAddress((void**)&wq0, g_wq0);
    cudaGetSymbolAddress((void**)&wq1, g_wq1);
    cudaGetSymbolAddress((void**)&wk0, g_wk0);
    cudaGetSymbolAddress((void**)&wk1, g_wk1);
    cudaGetSymbolAddress((void**)&wv0, g_wv0);
    cudaGetSymbolAddress((void**)&wv1, g_wv1);
    cudaGetSymbolAddress((void**)&wo0, g_wo0);
    cudaGetSymbolAddress((void**)&wo1, g_wo1);

    cudaFuncSetAttribute(attn_kernel,
                         cudaFuncAttributeMaxDynamicSharedMemorySize, ATTN_SMEM);
    cudaFuncSetAttribute(gemm_bf16_kernel,
                         cudaFuncAttributeMaxDynamicSharedMemorySize, GEMM_SMEM);

    const int nElem = MROWS * DD;
    fsplit_kernel<<<nElem / 4 / 256, 256>>>(x, x0, x1);
    dim3 tg(DD / 32, DD / 32), tb(32, 8);
    tsplit_kernel<<<tg, tb>>>(Wq, wq0, wq1);
    tsplit_kernel<<<tg, tb>>>(Wk, wk0, wk1);
    tsplit_kernel<<<tg, tb>>>(Wv, wv0, wv1);
    tsplit_kernel<<<tg, tb>>>(Wo, wo0, wo1);

    dim3 gg(DD / GN, MROWS / GM);   // (8, 32)
    gemm_bf16_kernel<<<gg, 256, GEMM_SMEM>>>(x0, x1, wq0, wq1, bq, q);
    gemm_bf16_kernel<<<gg, 256, GEMM_SMEM>>>(x0, x1, wk0, wk1, bk, k);
    gemm_bf16_kernel<<<gg, 256, GEMM_SMEM>>>(x0, x1, wv0, wv1, bv, v);

    attn_kernel<<<dim3(TT / AM, BB * HH), AM, ATTN_SMEM>>>(q, k, v, att);

    fsplit_kernel<<<nElem / 4 / 256, 256>>>(att, a0, a1);
    gemm_bf16_kernel<<<gg, 256, GEMM_SMEM>>>(a0, a1, wo0, wo1, bo, out);
}

// round 5
// speedup vs baseline: 3.6228x; 2.1592x over previous
#include <cuda_runtime.h>
#include <cuda_bf16.h>
#include <math.h>
#include <stdint.h>

#define BB 2
#define TT 2048
#define DD 1024
#define HH 16
#define HD 64
#define MROWS (BB*TT)   // 4096

// ---------------------------------------------------------------------------
// Scratch (__device__ globals per allocation-free rule)
// ---------------------------------------------------------------------------
__device__ __nv_bfloat16 g_x0[MROWS*DD], g_x1[MROWS*DD];   // x split hi/lo
__device__ __nv_bfloat16 g_q0[MROWS*DD], g_q1[MROWS*DD];
__device__ __nv_bfloat16 g_k0[MROWS*DD], g_k1[MROWS*DD];
__device__ __nv_bfloat16 g_v0[MROWS*DD], g_v1[MROWS*DD];
__device__ __nv_bfloat16 g_a0[MROWS*DD], g_a1[MROWS*DD];   // attn out hi/lo
// transposed+split weights: [N=1024 rows, K=1024] bf16
__device__ __nv_bfloat16 g_wq0[DD*DD], g_wq1[DD*DD];
__device__ __nv_bfloat16 g_wk0[DD*DD], g_wk1[DD*DD];
__device__ __nv_bfloat16 g_wv0[DD*DD], g_wv1[DD*DD];
__device__ __nv_bfloat16 g_wo0[DD*DD], g_wo1[DD*DD];

// ---------------------------------------------------------------------------
// PTX helpers (baseline sm_103 ISA: cp.async / ldmatrix / mma.sync)
// ---------------------------------------------------------------------------
__device__ __forceinline__ uint32_t smem_u32(const void* p) {
    uint32_t a;
    asm("{ .reg .u64 t; cvta.to.shared.u64 t, %1; cvt.u32.u64 %0, t; }"
        : "=r"(a) : "l"(p));
    return a;
}

#define CP16(dst, src) \
    asm volatile("cp.async.cg.shared.global [%0], [%1], 16;" \
        :: "r"(dst), "l"(src) : "memory")
#define CP_COMMIT() asm volatile("cp.async.commit_group;" ::: "memory")
#define CP_WAIT1()  asm volatile("cp.async.wait_group 1;" ::: "memory")
#define CP_WAIT0()  asm volatile("cp.async.wait_group 0;" ::: "memory")

#define LDSM_X4(r, a) \
    asm volatile("ldmatrix.sync.aligned.m8n8.x4.shared.b16 {%0,%1,%2,%3}, [%4];" \
        : "=r"((r)[0]), "=r"((r)[1]), "=r"((r)[2]), "=r"((r)[3]) : "r"(a))
#define LDSM_X2(r, a) \
    asm volatile("ldmatrix.sync.aligned.m8n8.x2.shared.b16 {%0,%1}, [%2];" \
        : "=r"((r)[0]), "=r"((r)[1]) : "r"(a))
#define LDSM_X2_T(r, a) \
    asm volatile("ldmatrix.sync.aligned.m8n8.x2.trans.shared.b16 {%0,%1}, [%2];" \
        : "=r"((r)[0]), "=r"((r)[1]) : "r"(a))

#define MMA_BF16(c, a, b) \
    asm volatile("mma.sync.aligned.m16n8k16.row.col.f32.bf16.bf16.f32 " \
        "{%0,%1,%2,%3}, {%4,%5,%6,%7}, {%8,%9}, {%0,%1,%2,%3};" \
        : "+f"((c)[0]), "+f"((c)[1]), "+f"((c)[2]), "+f"((c)[3]) \
        : "r"((a)[0]), "r"((a)[1]), "r"((a)[2]), "r"((a)[3]), \
          "r"((b)[0]), "r"((b)[1]))

__device__ __forceinline__ void split2(float x, float y,
                                       uint32_t& hi, uint32_t& lo) {
    __nv_bfloat16 hx = __float2bfloat16(x);
    __nv_bfloat16 hy = __float2bfloat16(y);
    __nv_bfloat162 h2(hx, hy);
    __nv_bfloat162 l2(__float2bfloat16(x - __bfloat162float(hx)),
                      __float2bfloat16(y - __bfloat162float(hy)));
    hi = *(uint32_t*)&h2;
    lo = *(uint32_t*)&l2;
}

// ---------------------------------------------------------------------------
// Prep kernels
// ---------------------------------------------------------------------------
__global__ void fsplit_kernel(const float* __restrict__ X,
                              __nv_bfloat16* __restrict__ H,
                              __nv_bfloat16* __restrict__ L)
{
    const int i = (blockIdx.x * blockDim.x + threadIdx.x) * 4;
    float4 xv = *(const float4*)(X + i);
    uint32_t h0, l0, h1, l1;
    split2(xv.x, xv.y, h0, l0);
    split2(xv.z, xv.w, h1, l1);
    *(uint32_t*)(H + i)     = h0;  *(uint32_t*)(H + i + 2) = h1;
    *(uint32_t*)(L + i)     = l0;  *(uint32_t*)(L + i + 2) = l1;
}

// W[K,N] fp32 -> Wt[N,K] bf16 hi/lo
__global__ void tsplit_kernel(const float* __restrict__ W,
                              __nv_bfloat16* __restrict__ Th,
                              __nv_bfloat16* __restrict__ Tl)
{
    __shared__ float t[32][33];
    const int n0 = blockIdx.x * 32, k0 = blockIdx.y * 32;
    const int tx = threadIdx.x, ty = threadIdx.y;   // 32 x 8
    #pragma unroll
    for (int i = 0; i < 32; i += 8)
        t[ty + i][tx] = W[(size_t)(k0 + ty + i) * DD + n0 + tx];
    __syncthreads();
    #pragma unroll
    for (int i = 0; i < 32; i += 8) {
        float x = t[tx][ty + i];
        __nv_bfloat16 h = __float2bfloat16(x);
        const size_t o = (size_t)(n0 + ty + i) * DD + k0 + tx;
        Th[o] = h;
        Tl[o] = __float2bfloat16(x - __bfloat162float(h));
    }
}

// ---------------------------------------------------------------------------
// bf16 HMMA GEMM, 3-term split. BF16OUT: write hi/lo bf16 instead of fp32.
// ---------------------------------------------------------------------------
#define GM 128
#define GN 128
#define GBK 32
#define NKT (DD / GBK)      // 32
#define SSTRB 80
#define OMAT (128 * SSTRB)
#define OA1 (OMAT)
#define OB0 (2*OMAT)
#define OB1 (3*OMAT)
#define STAGE (4*OMAT)
#define GEMM_SMEM (2*STAGE) // 81920 B

template<bool BF16OUT>
__global__ __launch_bounds__(256, 1) void gemm_bf16_kernel(
    const __nv_bfloat16* __restrict__ A0, const __nv_bfloat16* __restrict__ A1,
    const __nv_bfloat16* __restrict__ B0, const __nv_bfloat16* __restrict__ B1,
    const float* __restrict__ bias, float* __restrict__ C,
    __nv_bfloat16* __restrict__ Ch, __nv_bfloat16* __restrict__ Cl)
{
    extern __shared__ char smem[];
    const uint32_t sb = smem_u32(smem);
    const int tid  = threadIdx.x;
    const int wid  = tid >> 5;
    const int lane = tid & 31;
    const int wm   = wid >> 2;
    const int wn   = wid & 3;
    const int lr   = lane >> 2;
    const int lc   = lane & 3;
    const int m0 = blockIdx.y * GM;
    const int n0 = blockIdx.x * GN;

    const int lrow = tid >> 1;
    const int lcb  = (tid & 1) * 32;
    const uint32_t dstoff = lrow * SSTRB + lcb;
    const __nv_bfloat16* gA0 = A0 + (size_t)(m0 + lrow) * DD + lcb / 2;
    const __nv_bfloat16* gA1 = A1 + (size_t)(m0 + lrow) * DD + lcb / 2;
    const __nv_bfloat16* gB0 = B0 + (size_t)(n0 + lrow) * DD + lcb / 2;
    const __nv_bfloat16* gB1 = B1 + (size_t)(n0 + lrow) * DD + lcb / 2;

    const uint32_t a_base = sb + (uint32_t)(wm * 64 + (lane & 15)) * SSTRB
                          + (uint32_t)(lane >> 4) * 16;
    const uint32_t b_base = sb + OB0 + (uint32_t)(wn * 32 + (lane & 7)) * SSTRB
                          + (uint32_t)((lane >> 3) & 1) * 16;

    float c[4][4][4];
    #pragma unroll
    for (int mt = 0; mt < 4; mt++)
        #pragma unroll
        for (int nt = 0; nt < 4; nt++)
            #pragma unroll
            for (int i = 0; i < 4; i++) c[mt][nt][i] = 0.f;

    {
        const uint32_t s = sb + dstoff;
        CP16(s,            gA0);      CP16(s + 16,       gA0 + 8);
        CP16(s + OA1,      gA1);      CP16(s + OA1 + 16, gA1 + 8);
        CP16(s + OB0,      gB0);      CP16(s + OB0 + 16, gB0 + 8);
        CP16(s + OB1,      gB1);      CP16(s + OB1 + 16, gB1 + 8);
        CP_COMMIT();
    }

    for (int kt = 0; kt < NKT; kt++) {
        if (kt + 1 < NKT) {
            const uint32_t s = sb + ((kt + 1) & 1) * STAGE + dstoff;
            const int ko = (kt + 1) * GBK;
            CP16(s,            gA0 + ko);  CP16(s + 16,       gA0 + ko + 8);
            CP16(s + OA1,      gA1 + ko);  CP16(s + OA1 + 16, gA1 + ko + 8);
            CP16(s + OB0,      gB0 + ko);  CP16(s + OB0 + 16, gB0 + ko + 8);
            CP16(s + OB1,      gB1 + ko);  CP16(s + OB1 + 16, gB1 + ko + 8);
            CP_COMMIT();
            CP_WAIT1();
        } else {
            CP_WAIT0();
        }
        __syncthreads();

        const uint32_t st = ((uint32_t)(kt & 1)) * STAGE;
        #pragma unroll
        for (int ks = 0; ks < 2; ks++) {
            const uint32_t ksb = st + ks * 32;
            uint32_t ah[4][4], al[4][4], bh[4][2], bl[4][2];
            #pragma unroll
            for (int mt = 0; mt < 4; mt++) {
                const uint32_t aa = a_base + ksb + (uint32_t)(mt * 16) * SSTRB;
                LDSM_X4(ah[mt], aa);
                LDSM_X4(al[mt], aa + OA1);
            }
            #pragma unroll
            for (int nt = 0; nt < 4; nt++) {
                const uint32_t ba = b_base + ksb + (uint32_t)(nt * 8) * SSTRB;
                LDSM_X2(bh[nt], ba);
                LDSM_X2(bl[nt], ba + OMAT);
            }
            #pragma unroll
            for (int mt = 0; mt < 4; mt++)
                #pragma unroll
                for (int nt = 0; nt < 4; nt++) {
                    MMA_BF16(c[mt][nt], ah[mt], bh[nt]);
                    MMA_BF16(c[mt][nt], ah[mt], bl[nt]);
                    MMA_BF16(c[mt][nt], al[mt], bh[nt]);
                }
        }
        __syncthreads();
    }

    #pragma unroll
    for (int mt = 0; mt < 4; mt++) {
        const int row = m0 + wm * 64 + mt * 16 + lr;
        #pragma unroll
        for (int nt = 0; nt < 4; nt++) {
            const int col = n0 + wn * 32 + nt * 8 + 2 * lc;
            const float b0 = bias[col], b1 = bias[col + 1];
            const float o00 = c[mt][nt][0] + b0, o01 = c[mt][nt][1] + b1;
            const float o10 = c[mt][nt][2] + b0, o11 = c[mt][nt][3] + b1;
            if (BF16OUT) {
                uint32_t h, l;
                split2(o00, o01, h, l);
                *(uint32_t*)(Ch + (size_t)row * DD + col) = h;
                *(uint32_t*)(Cl + (size_t)row * DD + col) = l;
                split2(o10, o11, h, l);
                *(uint32_t*)(Ch + (size_t)(row + 8) * DD + col) = h;
                *(uint32_t*)(Cl + (size_t)(row + 8) * DD + col) = l;
            } else {
                *(float2*)(C + (size_t)row * DD + col)       = make_float2(o00, o01);
                *(float2*)(C + (size_t)(row + 8) * DD + col) = make_float2(o10, o11);
            }
        }
    }
}

// ---------------------------------------------------------------------------
// Tensor-core flash attention (causal, hd=64), bf16 hi/lo split everywhere.
// Br=128 (8 warps x 16 rows), Bc=64, double-buffered K/V via cp.async.
// ---------------------------------------------------------------------------
#define FRS 144                   // smem row stride bytes (128 + 16 pad)
#define FOQ1 (128*FRS)
#define FOKV (2*128*FRS)          // 36864
#define FSTG (4*64*FRS)           // 36864 per stage
#define FOK1 (64*FRS)
#define FOV0 (2*64*FRS)
#define FOV1 (3*64*FRS)
#define FATTN_SMEM (FOKV + 2*FSTG)   // 110592

__device__ __forceinline__ void load_kv_tile(
    uint32_t sb, int stg,
    const __nv_bfloat16* K0g, const __nv_bfloat16* K1g,
    const __nv_bfloat16* V0g, const __nv_bfloat16* V1g,
    size_t gbase, int tid)
{
    const uint32_t base = sb + FOKV + (uint32_t)stg * FSTG;
    #pragma unroll
    for (int it = 0; it < 8; it++) {
        const int i2 = ((it & 1) << 8) + tid;        // 0..511
        const int r  = i2 >> 3;
        const int cb = (i2 & 7) * 16;
        const __nv_bfloat16* sp;
        uint32_t off;
        if      ((it >> 1) == 0) { sp = K0g; off = 0;    }
        else if ((it >> 1) == 1) { sp = K1g; off = FOK1; }
        else if ((it >> 1) == 2) { sp = V0g; off = FOV0; }
        else                     { sp = V1g; off = FOV1; }
        CP16(base + off + (uint32_t)r * FRS + cb,
             sp + gbase + (size_t)r * DD + cb / 2);
    }
    CP_COMMIT();
}

__global__ __launch_bounds__(256, 1) void fattn_kernel(
    const __nv_bfloat16* __restrict__ Q0g, const __nv_bfloat16* __restrict__ Q1g,
    const __nv_bfloat16* __restrict__ K0g, const __nv_bfloat16* __restrict__ K1g,
    const __nv_bfloat16* __restrict__ V0g, const __nv_bfloat16* __restrict__ V1g,
    __nv_bfloat16* __restrict__ A0out, __nv_bfloat16* __restrict__ A1out)
{
    extern __shared__ char smem[];
    const uint32_t sb = smem_u32(smem);
    const int tid  = threadIdx.x;
    const int wid  = tid >> 5;
    const int lane = tid & 31;
    const int gid  = lane >> 2;     // 0..7
    const int t4   = lane & 3;      // 0..3

    const int qtile = (gridDim.x - 1) - blockIdx.x;   // heavy tiles first
    const int q0 = qtile * 128;
    const int b  = blockIdx.y >> 4;
    const int h  = blockIdx.y & 15;
    const size_t hb = (size_t)(b * TT) * DD + h * HD;

    // ---- load Q tile (128 rows x 64 bf16, hi+lo) ----
    #pragma unroll
    for (int it = 0; it < 8; it++) {
        const int i2 = ((it & 3) << 8) + tid;   // 0..1023
        const int r  = i2 >> 3;
        const int cb = (i2 & 7) * 16;
        const __nv_bfloat16* sp = (it >> 2) ? Q1g : Q0g;
        const uint32_t off = (it >> 2) ? FOQ1 : 0;
        CP16(sb + off + (uint32_t)r * FRS + cb,
             sp + hb + (size_t)(q0 + r) * DD + cb / 2);
    }
    CP_COMMIT();

    const int ntiles = q0 / 64 + 2;
    load_kv_tile(sb, 0, K0g, K1g, V0g, V1g, hb, tid);

    // fragment smem address bases
    const uint32_t qa0 = sb + (uint32_t)(wid * 16 + (lane & 15)) * FRS
                       + (uint32_t)(lane >> 4) * 16;
    const uint32_t qa1 = qa0 + FOQ1;
    const uint32_t kb  = sb + FOKV + (uint32_t)(lane & 7) * FRS
                       + (uint32_t)((lane >> 3) & 1) * 16;
    const uint32_t vb  = sb + FOKV + FOV0 + (uint32_t)(lane & 15) * FRS;

    float oc[8][4];
    #pragma unroll
    for (int nt = 0; nt < 8; nt++)
        #pragma unroll
        for (int e = 0; e < 4; e++) oc[nt][e] = 0.f;
    float m0v = -1e30f, m1v = -1e30f, l0 = 0.f, l1 = 0.f;

    const int r0 = q0 + wid * 16 + gid;
    const int r1 = r0 + 8;

    for (int kt = 0; kt < ntiles; kt++) {
        const int kv0 = kt * 64;
        if (kt + 1 < ntiles) {
            load_kv_tile(sb, (kt + 1) & 1, K0g, K1g, V0g, V1g,
                         hb + (size_t)(kv0 + 64) * DD, tid);
            CP_WAIT1();
        } else {
            CP_WAIT0();
        }
        __syncthreads();

        const uint32_t stg = (uint32_t)(kt & 1) * FSTG;

        // ---- S = Q K^T (3-term split) ----
        float sc[8][4];
        #pragma unroll
        for (int nt = 0; nt < 8; nt++)
            #pragma unroll
            for (int e = 0; e < 4; e++) sc[nt][e] = 0.f;

        #pragma unroll
        for (int ks = 0; ks < 4; ks++) {
            uint32_t ah[4], al[4];
            LDSM_X4(ah, qa0 + ks * 32);
            LDSM_X4(al, qa1 + ks * 32);
            #pragma unroll
            for (int nt = 0; nt < 8; nt++) {
                uint32_t bh[2], bl[2];
                const uint32_t ka = kb + stg + (uint32_t)(nt * 8) * FRS + ks * 32;
                LDSM_X2(bh, ka);
                LDSM_X2(bl, ka + FOK1);
                MMA_BF16(sc[nt], ah, bh);
                MMA_BF16(sc[nt], ah, bl);
                MMA_BF16(sc[nt], al, bh);
            }
        }

        // ---- scale + causal mask ----
        const bool maskt = (kt >= ntiles - 2);
        #pragma unroll
        for (int nt = 0; nt < 8; nt++) {
            #pragma unroll
            for (int e = 0; e < 4; e++) {
                float s = sc[nt][e] * 0.125f;
                if (maskt) {
                    const int col = kv0 + nt * 8 + 2 * t4 + (e & 1);
                    const int row = (e < 2) ? r0 : r1;
                    if (col > row) s = -1e30f;
                }
                sc[nt][e] = s;
            }
        }

        // ---- online softmax ----
        float mx0 = -1e30f, mx1 = -1e30f;
        #pragma unroll
        for (int nt = 0; nt < 8; nt++) {
            mx0 = fmaxf(mx0, fmaxf(sc[nt][0], sc[nt][1]));
            mx1 = fmaxf(mx1, fmaxf(sc[nt][2], sc[nt][3]));
        }
        mx0 = fmaxf(mx0, __shfl_xor_sync(0xffffffffu, mx0, 1));
        mx0 = fmaxf(mx0, __shfl_xor_sync(0xffffffffu, mx0, 2));
        mx1 = fmaxf(mx1, __shfl_xor_sync(0xffffffffu, mx1, 1));
        mx1 = fmaxf(mx1, __shfl_xor_sync(0xffffffffu, mx1, 2));

        const float mn0 = fmaxf(m0v, mx0);
        const float mn1 = fmaxf(m1v, mx1);
        const float al0 = __expf(m0v - mn0);
        const float al1 = __expf(m1v - mn1);

        float s0 = 0.f, s1 = 0.f;
        #pragma unroll
        for (int nt = 0; nt < 8; nt++) {
            sc[nt][0] = __expf(sc[nt][0] - mn0);
            sc[nt][1] = __expf(sc[nt][1] - mn0);
            sc[nt][2] = __expf(sc[nt][2] - mn1);
            sc[nt][3] = __expf(sc[nt][3] - mn1);
            s0 += sc[nt][0] + sc[nt][1];
            s1 += sc[nt][2] + sc[nt][3];
        }
        s0 += __shfl_xor_sync(0xffffffffu, s0, 1);
        s0 += __shfl_xor_sync(0xffffffffu, s0, 2);
        s1 += __shfl_xor_sync(0xffffffffu, s1, 1);
        s1 += __shfl_xor_sync(0xffffffffu, s1, 2);
        l0 = l0 * al0 + s0;
        l1 = l1 * al1 + s1;
        #pragma unroll
        for (int nt = 0; nt < 8; nt++) {
            oc[nt][0] *= al0;
            oc[nt][1] *= al0;
            oc[nt][2] *= al1;
            oc[nt][3] *= al1;
        }
        m0v = mn0;
        m1v = mn1;

        // ---- O += P V (3-term split) ----
        #pragma unroll
        for (int t = 0; t < 4; t++) {
            uint32_t ph[4], pl[4];
            split2(sc[2*t][0],   sc[2*t][1],   ph[0], pl[0]);
            split2(sc[2*t][2],   sc[2*t][3],   ph[1], pl[1]);
            split2(sc[2*t+1][0], sc[2*t+1][1], ph[2], pl[2]);
            split2(sc[2*t+1][2], sc[2*t+1][3], ph[3], pl[3]);
            #pragma unroll
            for (int nt = 0; nt < 8; nt++) {
                uint32_t bh[2], bl[2];
                const uint32_t va = vb + stg + (uint32_t)(t * 16) * FRS + nt * 16;
                LDSM_X2_T(bh, va);
                LDSM_X2_T(bl, va + FOK1);   // V1 = V0 + 64*FRS
                MMA_BF16(oc[nt], ph, bh);
                MMA_BF16(oc[nt], ph, bl);
                MMA_BF16(oc[nt], pl, bh);
            }
        }
        __syncthreads();   // keep compute done before next prefetch overwrites
    }

    // ---- epilogue: normalize + write hi/lo bf16 ----
    const float inv0 = 1.f / l0;
    const float inv1 = 1.f / l1;
    #pragma unroll
    for (int nt = 0; nt < 8; nt++) {
        const int col = nt * 8 + 2 * t4;
        uint32_t hh, ll;
        split2(oc[nt][0] * inv0, oc[nt][1] * inv0, hh, ll);
        *(uint32_t*)(A0out + hb + (size_t)r0 * DD + col) = hh;
        *(uint32_t*)(A1out + hb + (size_t)r0 * DD + col) = ll;
        split2(oc[nt][2] * inv1, oc[nt][3] * inv1, hh, ll);
        *(uint32_t*)(A0out + hb + (size_t)r1 * DD + col) = hh;
        *(uint32_t*)(A1out + hb + (size_t)r1 * DD + col) = ll;
    }
}

// ---------------------------------------------------------------------------
extern "C" void kernel_launch(void* const* d_in, const int* in_sizes, int n_in,
                              void* d_out, int out_size)
{
    (void)in_sizes; (void)n_in; (void)out_size;
    const float* x  = (const float*)d_in[0];
    const float* Wq = (const float*)d_in[2];
    const float* bq = (const float*)d_in[3];
    const float* Wk = (const float*)d_in[4];
    const float* bk = (const float*)d_in[5];
    const float* Wv = (const float*)d_in[6];
    const float* bv = (const float*)d_in[7];
    const float* Wo = (const float*)d_in[8];
    const float* bo = (const float*)d_in[9];
    float* out = (float*)d_out;

    __nv_bfloat16 *x0, *x1, *q0, *q1, *k0, *k1, *v0, *v1, *a0, *a1;
    cudaGetSymbolAddress((void**)&x0, g_x0);
    cudaGetSymbolAddress((void**)&x1, g_x1);
    cudaGetSymbolAddress((void**)&q0, g_q0);
    cudaGetSymbolAddress((void**)&q1, g_q1);
    cudaGetSymbolAddress((void**)&k0, g_k0);
    cudaGetSymbolAddress((void**)&k1, g_k1);
    cudaGetSymbolAddress((void**)&v0, g_v0);
    cudaGetSymbolAddress((void**)&v1, g_v1);
    cudaGetSymbolAddress((void**)&a0, g_a0);
    cudaGetSymbolAddress((void**)&a1, g_a1);
    __nv_bfloat16 *wq0, *wq1, *wk0, *wk1, *wv0, *wv1, *wo0, *wo1;
    cudaGetSymbolAddress((void**)&wq0, g_wq0);
    cudaGetSymbolAddress((void**)&wq1, g_wq1);
    cudaGetSymbolAddress((void**)&wk0, g_wk0);
    cudaGetSymbolAddress((void**)&wk1, g_wk1);
    cudaGetSymbolAddress((void**)&wv0, g_wv0);
    cudaGetSymbolAddress((void**)&wv1, g_wv1);
    cudaGetSymbolAddress((void**)&wo0, g_wo0);
    cudaGetSymbolAddress((void**)&wo1, g_wo1);

    cudaFuncSetAttribute(gemm_bf16_kernel<true>,
                         cudaFuncAttributeMaxDynamicSharedMemorySize, GEMM_SMEM);
    cudaFuncSetAttribute(gemm_bf16_kernel<false>,
                         cudaFuncAttributeMaxDynamicSharedMemorySize, GEMM_SMEM);
    cudaFuncSetAttribute(fattn_kernel,
                         cudaFuncAttributeMaxDynamicSharedMemorySize, FATTN_SMEM);

    const int nElem = MROWS * DD;
    fsplit_kernel<<<nElem / 4 / 256, 256>>>(x, x0, x1);
    dim3 tg(DD / 32, DD / 32), tb(32, 8);
    tsplit_kernel<<<tg, tb>>>(Wq, wq0, wq1);
    tsplit_kernel<<<tg, tb>>>(Wk, wk0, wk1);
    tsplit_kernel<<<tg, tb>>>(Wv, wv0, wv1);
    tsplit_kernel<<<tg, tb>>>(Wo, wo0, wo1);

    dim3 gg(DD / GN, MROWS / GM);   // (8, 32)
    gemm_bf16_kernel<true><<<gg, 256, GEMM_SMEM>>>(x0, x1, wq0, wq1, bq,
                                                   nullptr, q0, q1);
    gemm_bf16_kernel<true><<<gg, 256, GEMM_SMEM>>>(x0, x1, wk0, wk1, bk,
                                                   nullptr, k0, k1);
    gemm_bf16_kernel<true><<<gg, 256, GEMM_SMEM>>>(x0, x1, wv0, wv1, bv,
                                                   nullptr, v0, v1);

    fattn_kernel<<<dim3(TT / 128, BB * HH), 256, FATTN_SMEM>>>(
        q0, q1, k0, k1, v0, v1, a0, a1);

    gemm_bf16_kernel<false><<<gg, 256, GEMM_SMEM>>>(a0, a1, wo0, wo1, bo,
                                                    out, nullptr, nullptr);
}